// round 2
// baseline (speedup 1.0000x reference)
#include <cuda_runtime.h>
#include <cuda_fp16.h>
#include <cuda_bf16.h>

// Inputs (metadata order):
// 0: nbr_ids   [N]  int32
// 1: seg_ids   [N]  int32   (unused; degree = N/G)
// 2: batch_idx [G]  int32
// 3: pos_idx   [G]  int32
// 4: s_tem     [B]  int32
// 5: r_tem     [B]  int32
// 6: dt_flat   [G]  float32
// 7: ent_embeds [NUM_ENTS*D] float32
// 8: rel_embeds [NUM_RELS*D] float32
// Output: [ s_embed_seq (G*3D floats) | s_hist_dt_seq (G floats) ]

// fp16 shadow of the entity table (scratch; 16M halves = 32 MB cap)
#define F16_CAP (16 * 1024 * 1024)
__device__ __half g_ent_f16[F16_CAP];

// ---------------- fp32 -> fp16 table conversion ----------------
__global__ void __launch_bounds__(256)
convert_f16_kernel(const float4* __restrict__ src, int n4)
{
    int i = blockIdx.x * 256 + threadIdx.x;
    if (i >= n4) return;
    float4 v = __ldcs(src + i);               // streaming read: don't cache fp32 table
    __half2 a = __floats2half2_rn(v.x, v.y);
    __half2 b = __floats2half2_rn(v.z, v.w);
    uint2 o;
    o.x = *reinterpret_cast<unsigned*>(&a);
    o.y = *reinterpret_cast<unsigned*>(&b);
    reinterpret_cast<uint2*>(g_ent_f16)[i] = o;
}

// ---------------- Fast path: DEG==32, D==256, fp16 gather ----------------
// One warp per group. Lane l owns dims [8l, 8l+8). Neighbor ids distributed
// one per lane, broadcast with shfl (no smem, no CTA barrier).
__global__ void __launch_bounds__(256)
agg_f16_kernel(const int* __restrict__ nbr_ids,
               const int* __restrict__ batch_idx,
               const int* __restrict__ pos_idx,
               const int* __restrict__ s_tem,
               const int* __restrict__ r_tem,
               const float* __restrict__ dt_flat,
               const float4* __restrict__ ent,    // fp32, row stride 64 float4
               const float4* __restrict__ rel,    // fp32, row stride 64 float4
               float4* __restrict__ out_embed,    // row stride 192 float4
               float* __restrict__ out_dt,
               int S)
{
    const int warp = threadIdx.x >> 5;
    const int lane = threadIdx.x & 31;
    const int g    = (blockIdx.x << 3) + warp;   // 8 groups per block

    const int my_id = nbr_ids[(g << 5) + lane];  // coalesced: one id per lane

    const uint4* tab = reinterpret_cast<const uint4*>(g_ent_f16); // row = 32 uint4

    float acc[8];
#pragma unroll
    for (int k = 0; k < 8; ++k) acc[k] = 0.f;

#pragma unroll
    for (int j = 0; j < 32; ++j) {
        int id = __shfl_sync(0xffffffffu, my_id, j);
        uint4 v = __ldg(&tab[(id << 5) + lane]); // 16B = 8 halves
        const __half2* h = reinterpret_cast<const __half2*>(&v);
#pragma unroll
        for (int k = 0; k < 4; ++k) {
            float2 f = __half22float2(h[k]);
            acc[2 * k]     += f.x;
            acc[2 * k + 1] += f.y;
        }
    }
    const float inv = 1.0f / 32.0f;

    const int b = batch_idx[g];
    const int p = pos_idx[g];
    const int s = s_tem[b];
    const int r = r_tem[b];
    const int obase = (b * S + p) * 192;

    float4 m0 = make_float4(acc[0] * inv, acc[1] * inv, acc[2] * inv, acc[3] * inv);
    float4 m1 = make_float4(acc[4] * inv, acc[5] * inv, acc[6] * inv, acc[7] * inv);
    float4 s0 = __ldg(&ent[(s << 6) + 2 * lane]);
    float4 s1 = __ldg(&ent[(s << 6) + 2 * lane + 1]);
    float4 r0 = __ldg(&rel[(r << 6) + 2 * lane]);
    float4 r1 = __ldg(&rel[(r << 6) + 2 * lane + 1]);

    // streaming stores: output is write-once; keep fp16 table resident in L2
    __stcs(&out_embed[obase + 2 * lane],           m0);
    __stcs(&out_embed[obase + 2 * lane + 1],       m1);
    __stcs(&out_embed[obase + 64 + 2 * lane],      s0);
    __stcs(&out_embed[obase + 64 + 2 * lane + 1],  s1);
    __stcs(&out_embed[obase + 128 + 2 * lane],     r0);
    __stcs(&out_embed[obase + 128 + 2 * lane + 1], r1);

    if (lane == 0) out_dt[b * S + p] = dt_flat[g];
}

// ---------------- Generic fallback: any DEG / D, fp32 ----------------
__global__ void agg_generic_kernel(const int* __restrict__ nbr_ids,
                                   const int* __restrict__ batch_idx,
                                   const int* __restrict__ pos_idx,
                                   const int* __restrict__ s_tem,
                                   const int* __restrict__ r_tem,
                                   const float* __restrict__ dt_flat,
                                   const float* __restrict__ ent,
                                   const float* __restrict__ rel,
                                   float* __restrict__ out_embed,
                                   float* __restrict__ out_dt,
                                   int S, int D, int DEG)
{
    const int g = blockIdx.x;
    const int b = batch_idx[g];
    const int p = pos_idx[g];
    const long obase = (long)(b * S + p) * (3L * D);
    const float inv = 1.0f / (float)DEG;

    for (int d = threadIdx.x; d < D; d += blockDim.x) {
        float sum = 0.f;
        for (int j = 0; j < DEG; ++j) {
            int id = nbr_ids[(long)g * DEG + j];
            sum += ent[(long)id * D + d];
        }
        out_embed[obase + d]         = sum * inv;
        out_embed[obase + D + d]     = ent[(long)s_tem[b] * D + d];
        out_embed[obase + 2 * D + d] = rel[(long)r_tem[b] * D + d];
    }
    if (threadIdx.x == 0) out_dt[b * S + p] = dt_flat[g];
}

extern "C" void kernel_launch(void* const* d_in, const int* in_sizes, int n_in,
                              void* d_out, int out_size)
{
    const int*   nbr_ids   = (const int*)  d_in[0];
    const int*   batch_idx = (const int*)  d_in[2];
    const int*   pos_idx   = (const int*)  d_in[3];
    const int*   s_tem     = (const int*)  d_in[4];
    const int*   r_tem     = (const int*)  d_in[5];
    const float* dt_flat   = (const float*)d_in[6];
    const float* ent       = (const float*)d_in[7];
    const float* rel       = (const float*)d_in[8];

    const int N    = in_sizes[0];
    const int G    = in_sizes[2];
    const int B    = in_sizes[4];
    const int ENTD = in_sizes[7];          // NUM_ENTS * D
    const int DEG  = N / G;
    const int S    = G / B;
    const int D    = ((out_size / G) - 1) / 3;

    float* out_embed = (float*)d_out;
    float* out_dt    = (float*)d_out + (long)G * 3L * D;

    if (DEG == 32 && D == 256 && (G & 7) == 0 && ENTD <= F16_CAP && (ENTD & 7) == 0) {
        const int n4 = ENTD >> 2;
        convert_f16_kernel<<<(n4 + 255) / 256, 256>>>((const float4*)ent, n4);
        agg_f16_kernel<<<G / 8, 256>>>(nbr_ids, batch_idx, pos_idx, s_tem, r_tem,
                                       dt_flat, (const float4*)ent, (const float4*)rel,
                                       (float4*)out_embed, out_dt, S);
    } else {
        agg_generic_kernel<<<G, 256>>>(nbr_ids, batch_idx, pos_idx, s_tem, r_tem,
                                       dt_flat, ent, rel, out_embed, out_dt,
                                       S, D, DEG);
    }
}